// round 2
// baseline (speedup 1.0000x reference)
#include <cuda_runtime.h>
#include <math.h>

#define N_SP 4096
#define C_IN 256
#define CQ   32
#define BATCH 4

// d_out layout (floats): q[0], k[524288], v[1048576], attended[5242880]
#define Q_OFF 0
#define K_OFF 524288
#define V_OFF 1048576
#define A_OFF 5242880

// Scratch (device globals: allowed; no dynamic allocation)
__device__ float g_attn_out[BATCH * C_IN * N_SP];  // 16 MB
__device__ float g_proj[BATCH * C_IN * N_SP];      // 16 MB

// ---------------------------------------------------------------------------
// Kernel 1: QKV projections.  Out[o][n] = sum_c W[o][c] * x[b][c][n]
// Grid: (ntiles=64, otiles=10, b=4). Block 256. Tile: 32 o x 64 n, K-tile 32.
// otile 0 -> q (32 rows), 1 -> k (32 rows), 2..9 -> v rows (ot-2)*32..
// ---------------------------------------------------------------------------
__global__ __launch_bounds__(256) void qkv_kernel(
    const float* __restrict__ x,
    const float* __restrict__ Wq,
    const float* __restrict__ Wk,
    const float* __restrict__ Wv,
    float* __restrict__ out)
{
    __shared__ float Wt[32 * 33];
    __shared__ float Xt[32 * 68];

    const int b  = blockIdx.z;
    const int ot = blockIdx.y;
    const int n0 = blockIdx.x * 64;

    const float* W;
    float* dst;
    if (ot == 0)      { W = Wq;                      dst = out + Q_OFF + (size_t)b * CQ   * N_SP; }
    else if (ot == 1) { W = Wk;                      dst = out + K_OFF + (size_t)b * CQ   * N_SP; }
    else              { W = Wv + (ot - 2) * 32 * C_IN;
                        dst = out + V_OFF + (size_t)b * C_IN * N_SP + (size_t)(ot - 2) * 32 * N_SP; }

    const float* xb = x + (size_t)b * C_IN * N_SP;

    const int t    = threadIdx.x;
    const int lane = t & 31;       // output row within tile
    const int warp = t >> 5;       // n-subtile (8 n each)

    float acc[8];
#pragma unroll
    for (int i = 0; i < 8; i++) acc[i] = 0.f;

    for (int c0 = 0; c0 < C_IN; c0 += 32) {
        // W tile [32 o][32 c], pad 33
        for (int i = t; i < 1024; i += 256) {
            int o = i >> 5, c = i & 31;
            Wt[o * 33 + c] = W[o * C_IN + c0 + c];
        }
        // X tile [32 c][64 n], pad 68
        for (int i = t; i < 2048; i += 256) {
            int c = i >> 6, n = i & 63;
            Xt[c * 68 + n] = xb[(size_t)(c0 + c) * N_SP + n0 + n];
        }
        __syncthreads();

#pragma unroll
        for (int c = 0; c < 32; c++) {
            float wv = Wt[lane * 33 + c];
            const float4 xv0 = *(const float4*)&Xt[c * 68 + warp * 8];
            const float4 xv1 = *(const float4*)&Xt[c * 68 + warp * 8 + 4];
            acc[0] += wv * xv0.x; acc[1] += wv * xv0.y;
            acc[2] += wv * xv0.z; acc[3] += wv * xv0.w;
            acc[4] += wv * xv1.x; acc[5] += wv * xv1.y;
            acc[6] += wv * xv1.z; acc[7] += wv * xv1.w;
        }
        __syncthreads();
    }

    float* drow = dst + (size_t)lane * N_SP + n0 + warp * 8;
    float4 r0 = make_float4(acc[0], acc[1], acc[2], acc[3]);
    float4 r1 = make_float4(acc[4], acc[5], acc[6], acc[7]);
    *(float4*)(drow)     = r0;
    *(float4*)(drow + 4) = r1;
}

// ---------------------------------------------------------------------------
// Kernel 2: flash attention.
//   S[n][m] = scale * sum_c q[c][n] k[c][m];  P = softmax_m(S);
//   O[c][n] = sum_m P[n][m] v[c][m]
// Block: 32 query rows. 256 threads. lane = query row, warp = 32-wide c-chunk.
// Each thread accumulates O for (row=lane, c in [warp*32, warp*32+32)).
// ---------------------------------------------------------------------------
__global__ __launch_bounds__(256) void attn_kernel(
    const float* __restrict__ qbuf,
    const float* __restrict__ kbuf,
    const float* __restrict__ vbuf)
{
    __shared__ float Qs[32 * 33];
    __shared__ float Ks[32 * 33];
    __shared__ float Ss[32 * 33];
    __shared__ float Vs[32 * 260];   // [m][c], pad 260 -> float4-aligned rows
    __shared__ float m_row[32], l_row[32], a_row[32];

    const int b  = blockIdx.y;
    const int n0 = blockIdx.x * 32;
    const int t    = threadIdx.x;
    const int lane = t & 31;
    const int warp = t >> 5;

    const float scale = 0.1767766952966369f;  // 32^-0.5

    const float* q = qbuf + (size_t)b * CQ   * N_SP;
    const float* k = kbuf + (size_t)b * CQ   * N_SP;
    const float* v = vbuf + (size_t)b * C_IN * N_SP;

    // Load Q tile (pre-scaled)
    for (int i = t; i < 1024; i += 256) {
        int c = i >> 5, n = i & 31;
        Qs[n * 33 + c] = q[(size_t)c * N_SP + n0 + n] * scale;
    }
    if (t < 32) { m_row[t] = -1e30f; l_row[t] = 0.f; }

    float o[32];
#pragma unroll
    for (int j = 0; j < 32; j++) o[j] = 0.f;
    __syncthreads();

    for (int m0 = 0; m0 < N_SP; m0 += 32) {
        // K tile [m][c]
        for (int i = t; i < 1024; i += 256) {
            int c = i >> 5, m = i & 31;
            Ks[m * 33 + c] = k[(size_t)c * N_SP + m0 + m];
        }
        // V tile [m][c] (32 x 256)
        for (int i = t; i < 8192; i += 256) {
            int c = i >> 5, m = i & 31;
            Vs[m * 260 + c] = v[(size_t)c * N_SP + m0 + m];
        }
        __syncthreads();

        // S: thread computes rows n=lane, cols m = warp*4 .. +3
        {
            const int mb = warp * 4;
            float s0 = 0.f, s1 = 0.f, s2 = 0.f, s3 = 0.f;
#pragma unroll
            for (int c = 0; c < 32; c++) {
                float qv = Qs[lane * 33 + c];
                s0 += qv * Ks[(mb + 0) * 33 + c];
                s1 += qv * Ks[(mb + 1) * 33 + c];
                s2 += qv * Ks[(mb + 2) * 33 + c];
                s3 += qv * Ks[(mb + 3) * 33 + c];
            }
            Ss[lane * 33 + mb + 0] = s0;
            Ss[lane * 33 + mb + 1] = s1;
            Ss[lane * 33 + mb + 2] = s2;
            Ss[lane * 33 + mb + 3] = s3;
        }
        __syncthreads();

        // Online softmax: warp w owns rows 4w..4w+3 (lane-parallel over m)
#pragma unroll
        for (int rr = 0; rr < 4; rr++) {
            const int row = warp * 4 + rr;
            float s = Ss[row * 33 + lane];
            float mx = s;
#pragma unroll
            for (int off = 16; off; off >>= 1)
                mx = fmaxf(mx, __shfl_xor_sync(0xffffffffu, mx, off));
            float mold = m_row[row];
            float mnew = fmaxf(mold, mx);
            float p = __expf(s - mnew);
            float ps = p;
#pragma unroll
            for (int off = 16; off; off >>= 1)
                ps += __shfl_xor_sync(0xffffffffu, ps, off);
            Ss[row * 33 + lane] = p;
            if (lane == 0) {
                float alpha = __expf(mold - mnew);
                l_row[row] = alpha * l_row[row] + ps;
                m_row[row] = mnew;
                a_row[row] = alpha;
            }
        }
        __syncthreads();

        // Rescale + accumulate
        {
            float alpha = a_row[lane];
#pragma unroll
            for (int j = 0; j < 32; j++) o[j] *= alpha;

            const int cb = warp * 32;
#pragma unroll
            for (int mm = 0; mm < 32; mm++) {
                float p = Ss[lane * 33 + mm];
#pragma unroll
                for (int j = 0; j < 32; j += 4) {
                    const float4 vv = *(const float4*)&Vs[mm * 260 + cb + j];
                    o[j + 0] += p * vv.x;
                    o[j + 1] += p * vv.y;
                    o[j + 2] += p * vv.z;
                    o[j + 3] += p * vv.w;
                }
            }
        }
        __syncthreads();
    }

    const float inv = 1.f / l_row[lane];
    float* ob = g_attn_out + (size_t)b * C_IN * N_SP;
#pragma unroll
    for (int j = 0; j < 32; j++) {
        ob[(size_t)(warp * 32 + j) * N_SP + n0 + lane] = o[j] * inv;
    }
}

// ---------------------------------------------------------------------------
// Kernel 3: output projection.  proj[o][n] = sum_c Wp[o][c] * attn_out[c][n]
// Grid: (64 ntiles, 8 otiles, 4 b)
// ---------------------------------------------------------------------------
__global__ __launch_bounds__(256) void proj_kernel(const float* __restrict__ Wp)
{
    __shared__ float Wt[32 * 33];
    __shared__ float Xt[32 * 68];

    const int b  = blockIdx.z;
    const int ot = blockIdx.y;
    const int n0 = blockIdx.x * 64;

    const float* W  = Wp + ot * 32 * C_IN;
    const float* xb = g_attn_out + (size_t)b * C_IN * N_SP;
    float* dst      = g_proj + (size_t)b * C_IN * N_SP + (size_t)ot * 32 * N_SP;

    const int t    = threadIdx.x;
    const int lane = t & 31;
    const int warp = t >> 5;

    float acc[8];
#pragma unroll
    for (int i = 0; i < 8; i++) acc[i] = 0.f;

    for (int c0 = 0; c0 < C_IN; c0 += 32) {
        for (int i = t; i < 1024; i += 256) {
            int o = i >> 5, c = i & 31;
            Wt[o * 33 + c] = W[o * C_IN + c0 + c];
        }
        for (int i = t; i < 2048; i += 256) {
            int c = i >> 6, n = i & 63;
            Xt[c * 68 + n] = xb[(size_t)(c0 + c) * N_SP + n0 + n];
        }
        __syncthreads();

#pragma unroll
        for (int c = 0; c < 32; c++) {
            float wv = Wt[lane * 33 + c];
            const float4 xv0 = *(const float4*)&Xt[c * 68 + warp * 8];
            const float4 xv1 = *(const float4*)&Xt[c * 68 + warp * 8 + 4];
            acc[0] += wv * xv0.x; acc[1] += wv * xv0.y;
            acc[2] += wv * xv0.z; acc[3] += wv * xv0.w;
            acc[4] += wv * xv1.x; acc[5] += wv * xv1.y;
            acc[6] += wv * xv1.z; acc[7] += wv * xv1.w;
        }
        __syncthreads();
    }

    float* drow = dst + (size_t)lane * N_SP + n0 + warp * 8;
    *(float4*)(drow)     = make_float4(acc[0], acc[1], acc[2], acc[3]);
    *(float4*)(drow + 4) = make_float4(acc[4], acc[5], acc[6], acc[7]);
}

// ---------------------------------------------------------------------------
// Kernel 4: InstanceNorm (affine=False, biased var) + residual.
// One block per (b,c) row of 4096.
// ---------------------------------------------------------------------------
__global__ __launch_bounds__(256) void norm_kernel(
    const float* __restrict__ x,
    float* __restrict__ att_out)
{
    __shared__ float red[16];

    const size_t bc = blockIdx.x;
    const float4* p4 = (const float4*)(g_proj + bc * N_SP);
    const float4* x4 = (const float4*)(x + bc * N_SP);
    float4* o4       = (float4*)(att_out + bc * N_SP);

    const int t    = threadIdx.x;
    const int lane = t & 31;
    const int warp = t >> 5;

    float4 vals[4];
    float s = 0.f, sq = 0.f;
#pragma unroll
    for (int i = 0; i < 4; i++) {
        float4 v = p4[i * 256 + t];
        vals[i] = v;
        s  += v.x + v.y + v.z + v.w;
        sq += v.x * v.x + v.y * v.y + v.z * v.z + v.w * v.w;
    }
#pragma unroll
    for (int off = 16; off; off >>= 1) {
        s  += __shfl_xor_sync(0xffffffffu, s, off);
        sq += __shfl_xor_sync(0xffffffffu, sq, off);
    }
    if (lane == 0) { red[warp] = s; red[8 + warp] = sq; }
    __syncthreads();
    if (t == 0) {
        float ts = 0.f, tq = 0.f;
        for (int i = 0; i < 8; i++) { ts += red[i]; tq += red[8 + i]; }
        red[0] = ts; red[8] = tq;
    }
    __syncthreads();

    const float mean = red[0] * (1.f / N_SP);
    float var = red[8] * (1.f / N_SP) - mean * mean;
    const float rstd = rsqrtf(var + 1e-5f);

#pragma unroll
    for (int i = 0; i < 4; i++) {
        float4 v  = vals[i];
        float4 xr = x4[i * 256 + t];
        float4 r;
        r.x = (v.x - mean) * rstd + xr.x;
        r.y = (v.y - mean) * rstd + xr.y;
        r.z = (v.z - mean) * rstd + xr.z;
        r.w = (v.w - mean) * rstd + xr.w;
        o4[i * 256 + t] = r;
    }
}

// ---------------------------------------------------------------------------
extern "C" void kernel_launch(void* const* d_in, const int* in_sizes, int n_in,
                              void* d_out, int out_size)
{
    const float* x  = (const float*)d_in[0];
    const float* Wq = (const float*)d_in[1];
    const float* Wk = (const float*)d_in[2];
    const float* Wv = (const float*)d_in[3];
    const float* Wp = (const float*)d_in[4];
    float* out = (float*)d_out;

    qkv_kernel<<<dim3(64, 10, BATCH), 256>>>(x, Wq, Wk, Wv, out);
    attn_kernel<<<dim3(N_SP / 32, BATCH), 256>>>(out + Q_OFF, out + K_OFF, out + V_OFF);
    proj_kernel<<<dim3(64, 8, BATCH), 256>>>(Wp);
    norm_kernel<<<BATCH * C_IN, 256>>>(x, out + A_OFF);
}